// round 1
// baseline (speedup 1.0000x reference)
#include <cuda_runtime.h>
#include <cstdio>

// ---------------- problem constants ----------------
#define BATCH   64
#define DIMS    200      // n == d == 200
#define SIZEM   50
#define NUMQ    10000
#define LBERT   512
#define HBERT   768

// output layout: p [B*n], Mv [B*(n+1)*m*d], w [B*n*m]
#define OFF_P   0
#define OFF_MV  (BATCH*DIMS)                              // 12800
#define OFF_W   (OFF_MV + BATCH*(DIMS+1)*SIZEM*DIMS)      // 12800 + 128640000

// ---------------- scratch (static device memory; no allocs allowed) ----------------
__device__ float g_T1  [BATCH*LBERT*DIMS];   // em pre-transpose  [B,512,200]
__device__ float g_emat[BATCH*DIMS*DIMS];    // em_at             [B,200,200]
__device__ float g_k   [BATCH*DIMS*DIMS];    // gathered k        [B,200,200]
__device__ float g_v   [BATCH*DIMS*DIMS];    // gathered v
__device__ float g_e   [BATCH*DIMS*DIMS];    // sigmoid gate
__device__ float g_a   [BATCH*DIMS*DIMS];    // tanh add
__device__ float g_read[BATCH*DIMS*DIMS];    // read vectors
__device__ float g_f   [BATCH*DIMS*DIMS];    // f
__device__ float g_fl  [BATCH*DIMS*DIMS];    // f_l (pre-transpose, [b,i,c])

// ---------------- gather v rows ----------------
__global__ void gather_v_kernel(const int* __restrict__ q, const int* __restrict__ r,
                                const float* __restrict__ v_emb, float* __restrict__ vbuf)
{
    int m   = blockIdx.x;                  // b*200+i
    int tid = threadIdx.x;                 // 64
    int x   = q[m] + NUMQ * r[m];
    const float4* src = (const float4*)(v_emb + (size_t)x * DIMS);
    float4*       dst = (float4*)(vbuf + (size_t)m * DIMS);
    for (int i = tid; i < DIMS/4; i += 64) dst[i] = src[i];
}

// ---------------- w = softmax(k @ Mk^T), fused k gather ----------------
__global__ void wk_kernel(const int* __restrict__ q, const float* __restrict__ k_emb,
                          const float* __restrict__ Mk,
                          float* __restrict__ wOut, float* __restrict__ kbuf)
{
    int m   = blockIdx.x;                  // b*200+i
    int tid = threadIdx.x;                 // 256
    __shared__ float krow[DIMS];
    __shared__ float part4[200];
    __shared__ float logits[SIZEM];
    __shared__ float sm_max, sm_sum;

    int qi = q[m];
    if (tid < DIMS) {
        float val = k_emb[(size_t)qi * DIMS + tid];
        krow[tid] = val;
        kbuf[(size_t)m * DIMS + tid] = val;
    }
    __syncthreads();

    if (tid < 200) {
        int s = tid >> 2, g = tid & 3;
        const float* mk = Mk + s * DIMS + g * 50;
        const float* kr = krow + g * 50;
        float acc = 0.f;
        #pragma unroll 10
        for (int kk = 0; kk < 50; ++kk) acc = fmaf(kr[kk], __ldg(&mk[kk]), acc);
        part4[tid] = acc;
    }
    __syncthreads();
    if (tid < SIZEM)
        logits[tid] = part4[4*tid] + part4[4*tid+1] + part4[4*tid+2] + part4[4*tid+3];
    __syncthreads();
    if (tid < 32) {
        float v = logits[tid];
        if (tid + 32 < SIZEM) v = fmaxf(v, logits[tid + 32]);
        #pragma unroll
        for (int o = 16; o > 0; o >>= 1) v = fmaxf(v, __shfl_xor_sync(0xffffffff, v, o));
        if (tid == 0) sm_max = v;
    }
    __syncthreads();
    if (tid < SIZEM) logits[tid] = expf(logits[tid] - sm_max);
    __syncthreads();
    if (tid < 32) {
        float v = (tid < SIZEM) ? logits[tid] : 0.f;
        if (tid + 32 < SIZEM) v += logits[tid + 32];
        #pragma unroll
        for (int o = 16; o > 0; o >>= 1) v += __shfl_xor_sync(0xffffffff, v, o);
        if (tid == 0) sm_sum = v;
    }
    __syncthreads();
    if (tid < SIZEM) wOut[(size_t)m * SIZEM + tid] = logits[tid] / sm_sum;
}

// ---------------- generic NT SGEMM with optional concat-A and fused epilogue ----------------
// C[m,n] = act( sum_k A(m,k) * W[n,k] + bias[n] )
// A(m,k) = k < Ksplit ? A[m*Ksplit+k] : A2[m*(K-Ksplit)+k-Ksplit]
#define AS_STRIDE 68
template<int ACT>   // 0 none, 1 sigmoid, 2 tanh, 3 relu
__global__ void gemm_nt(const float* __restrict__ A, const float* __restrict__ A2,
                        const float* __restrict__ W, const float* __restrict__ bias,
                        float* __restrict__ C, int M, int N, int K, int Ksplit)
{
    __shared__ __align__(16) float As[16 * AS_STRIDE];
    __shared__ __align__(16) float Ws[16 * AS_STRIDE];
    int bm = blockIdx.y * 64;
    int bn = blockIdx.x * 64;
    int tid = threadIdx.x;                // 256
    int tm = (tid / 16) * 4;
    int tn = (tid % 16) * 4;
    int lk = tid % 16;
    int lm = tid / 16;
    int K2 = K - Ksplit;
    float acc[4][4] = {};

    for (int k0 = 0; k0 < K; k0 += 16) {
        int kg = k0 + lk;
        #pragma unroll
        for (int p = 0; p < 4; ++p) {
            int m = bm + lm + 16 * p;
            float v = 0.f;
            if (m < M && kg < K)
                v = (kg < Ksplit) ? A[(size_t)m * Ksplit + kg]
                                  : A2[(size_t)m * K2 + (kg - Ksplit)];
            As[lk * AS_STRIDE + lm + 16 * p] = v;
        }
        #pragma unroll
        for (int p = 0; p < 4; ++p) {
            int n = bn + lm + 16 * p;
            float v = (n < N && kg < K) ? W[(size_t)n * K + kg] : 0.f;
            Ws[lk * AS_STRIDE + lm + 16 * p] = v;
        }
        __syncthreads();
        #pragma unroll
        for (int kk = 0; kk < 16; ++kk) {
            float4 av = *(const float4*)&As[kk * AS_STRIDE + tm];
            float4 bv = *(const float4*)&Ws[kk * AS_STRIDE + tn];
            float aa[4] = {av.x, av.y, av.z, av.w};
            float bb[4] = {bv.x, bv.y, bv.z, bv.w};
            #pragma unroll
            for (int i = 0; i < 4; ++i)
                #pragma unroll
                for (int j = 0; j < 4; ++j)
                    acc[i][j] = fmaf(aa[i], bb[j], acc[i][j]);
        }
        __syncthreads();
    }
    #pragma unroll
    for (int i = 0; i < 4; ++i) {
        int m = bm + tm + i;
        if (m >= M) continue;
        #pragma unroll
        for (int j = 0; j < 4; ++j) {
            int n = bn + tn + j;
            if (n >= N) continue;
            float v = acc[i][j] + bias[n];
            if (ACT == 1) v = 1.f / (1.f + expf(-v));
            else if (ACT == 2) v = tanhf(v);
            else if (ACT == 3) v = fmaxf(v, 0.f);
            C[(size_t)m * N + n] = v;
        }
    }
}

// ---------------- batched TN SGEMM: C_b[i,j] = sum_l A_b[l,i] * W[j,l] + bias[j] ----------------
__global__ void gemm_tn_batched(const float* __restrict__ A, const float* __restrict__ W,
                                const float* __restrict__ bias, float* __restrict__ C,
                                int M, int N, int K)
{
    __shared__ __align__(16) float As[16 * AS_STRIDE];
    __shared__ __align__(16) float Ws[16 * AS_STRIDE];
    int bb = blockIdx.z;
    const float* Ab = A + (size_t)bb * K * M;
    float*       Cb = C + (size_t)bb * M * N;
    int bm = blockIdx.y * 64;
    int bn = blockIdx.x * 64;
    int tid = threadIdx.x;
    int tm = (tid / 16) * 4;
    int tn = (tid % 16) * 4;
    int mm = tid % 64;
    int kka = tid / 64;                   // 4 k-rows per pass
    int lk = tid % 16;
    int lm = tid / 16;
    float acc[4][4] = {};

    for (int k0 = 0; k0 < K; k0 += 16) {
        #pragma unroll
        for (int p = 0; p < 4; ++p) {
            int kg = k0 + kka + 4 * p;
            int m  = bm + mm;
            float v = (m < M && kg < K) ? Ab[(size_t)kg * M + m] : 0.f;
            As[(kka + 4 * p) * AS_STRIDE + mm] = v;
        }
        int kg = k0 + lk;
        #pragma unroll
        for (int p = 0; p < 4; ++p) {
            int n = bn + lm + 16 * p;
            float v = (n < N && kg < K) ? W[(size_t)n * K + kg] : 0.f;
            Ws[lk * AS_STRIDE + lm + 16 * p] = v;
        }
        __syncthreads();
        #pragma unroll
        for (int kk = 0; kk < 16; ++kk) {
            float4 av = *(const float4*)&As[kk * AS_STRIDE + tm];
            float4 bv = *(const float4*)&Ws[kk * AS_STRIDE + tn];
            float aa[4] = {av.x, av.y, av.z, av.w};
            float bb2[4] = {bv.x, bv.y, bv.z, bv.w};
            #pragma unroll
            for (int i = 0; i < 4; ++i)
                #pragma unroll
                for (int j = 0; j < 4; ++j)
                    acc[i][j] = fmaf(aa[i], bb2[j], acc[i][j]);
        }
        __syncthreads();
    }
    #pragma unroll
    for (int i = 0; i < 4; ++i) {
        int m = bm + tm + i;
        if (m >= M) continue;
        #pragma unroll
        for (int j = 0; j < 4; ++j) {
            int n = bn + tn + j;
            if (n >= N) continue;
            Cb[(size_t)m * N + n] = acc[i][j] + bias[n];
        }
    }
}

// ---------------- memory scan: Mv recurrence + pre-state emit + read einsum ----------------
// grid (4 j-chunks of 50, 64 batches), 256 threads
__global__ void scan_kernel(const float* __restrict__ w,     // [B,200,50]
                            const float* __restrict__ e,     // [B,200,200]
                            const float* __restrict__ a,     // [B,200,200]
                            const float* __restrict__ Mv0,   // [50,200]
                            float* __restrict__ MvOut,       // [B,201,50,200]
                            float* __restrict__ readOut)     // [B,200,200]
{
    const int cs = blockIdx.x;            // 0..3
    const int b  = blockIdx.y;            // 0..63
    const int j0 = cs * 50;
    __shared__ float Mv_s[SIZEM * 50];    // [s][j], 10 KB
    __shared__ float w_s[SIZEM], e_s[50], a_s[50];
    __shared__ float part[4 * 50];
    int tid = threadIdx.x;

    for (int idx = tid; idx < SIZEM * 50; idx += 256) {
        int s = idx / 50, j = idx % 50;
        Mv_s[idx] = Mv0[s * DIMS + j0 + j];
    }

    int sg = tid / 50;                    // s-group for update (tid<200)
    int j  = tid % 50;
    int scnt = 12 + (sg < 2 ? 1 : 0);
    int sst  = sg * 12 + min(sg, 2);

    for (int t = 0; t < DIMS; ++t) {
        __syncthreads();                  // init / prev-iter part read complete
        if (tid < 50) {
            w_s[tid] = w[((size_t)b * DIMS + t) * SIZEM + tid];
            e_s[tid] = e[((size_t)b * DIMS + t) * DIMS + j0 + tid];
            a_s[tid] = a[((size_t)b * DIMS + t) * DIMS + j0 + tid];
        }
        __syncthreads();
        // emit pre-update state (float2 vectorized, 1250 per block)
        {
            const float2* src = (const float2*)Mv_s;
            float* outb = MvOut + ((size_t)(b * (DIMS + 1) + t) * SIZEM) * DIMS + j0;
            for (int idx = tid; idx < 1250; idx += 256) {
                int s = idx / 25, c = idx % 25;
                *(float2*)(outb + s * DIMS + c * 2) = src[idx];
            }
        }
        __syncthreads();                  // all reads of old state done
        if (tid < 200) {
            float acc = 0.f, ej = e_s[j], aj = a_s[j];
            for (int s = sst; s < sst + scnt; ++s) {
                float m = Mv_s[s * 50 + j];
                float wv = w_s[s];
                acc = fmaf(wv, m, acc);
                // Mv*(1-w*e) + w*a = m + w*(a - e*m)
                Mv_s[s * 50 + j] = fmaf(wv, fmaf(-ej, m, aj), m);
            }
            part[sg * 50 + j] = acc;
        }
        __syncthreads();
        if (tid < 50) {
            readOut[((size_t)b * DIMS + t) * DIMS + j0 + tid] =
                part[tid] + part[50 + tid] + part[100 + tid] + part[150 + tid];
        }
    }
    __syncthreads();
    // final state at t = 200
    {
        const float2* src = (const float2*)Mv_s;
        float* outb = MvOut + ((size_t)(b * (DIMS + 1) + DIMS) * SIZEM) * DIMS + j0;
        for (int idx = tid; idx < 1250; idx += 256) {
            int s = idx / 25, c = idx % 25;
            *(float2*)(outb + s * DIMS + c * 2) = src[idx];
        }
    }
}

// ---------------- final p = sigmoid(concat(f, f_l^T) @ W_p + b_p) ----------------
__global__ void p_kernel(const float* __restrict__ f, const float* __restrict__ fl,
                         const float* __restrict__ Wp, const float* __restrict__ bp,
                         float* __restrict__ pOut)
{
    int bt = blockIdx.x;                  // b*200+t
    int b  = bt / DIMS, t = bt % DIMS;
    int tid = threadIdx.x;                // 128
    float acc = 0.f;
    for (int c = tid; c < 2 * DIMS; c += 128) {
        float xv = (c < DIMS) ? f[(size_t)bt * DIMS + c]
                              : fl[((size_t)b * DIMS + (c - DIMS)) * DIMS + t];
        acc = fmaf(Wp[c], xv, acc);
    }
    __shared__ float red[128];
    red[tid] = acc;
    __syncthreads();
    #pragma unroll
    for (int s = 64; s > 0; s >>= 1) {
        if (tid < s) red[tid] += red[tid + s];
        __syncthreads();
    }
    if (tid == 0) pOut[bt] = 1.f / (1.f + expf(-(red[0] + bp[0])));
}

// ---------------- launcher ----------------
extern "C" void kernel_launch(void* const* d_in, const int* in_sizes, int n_in,
                              void* d_out, int out_size)
{
    const int*   q     = (const int*)d_in[0];
    const int*   r     = (const int*)d_in[1];
    const float* bert  = (const float*)d_in[2];
    const float* k_emb = (const float*)d_in[3];
    const float* v_emb = (const float*)d_in[4];
    const float* Mk    = (const float*)d_in[5];
    const float* Mv0   = (const float*)d_in[6];
    const float* W_at  = (const float*)d_in[7];
    const float* b_at  = (const float*)d_in[8];
    const float* W_at2 = (const float*)d_in[9];
    const float* b_at2 = (const float*)d_in[10];
    const float* W_fus = (const float*)d_in[11];
    const float* b_fus = (const float*)d_in[12];
    const float* W_e   = (const float*)d_in[13];
    const float* b_e   = (const float*)d_in[14];
    const float* W_a   = (const float*)d_in[15];
    const float* b_a   = (const float*)d_in[16];
    const float* W_f   = (const float*)d_in[17];
    const float* b_f   = (const float*)d_in[18];
    const float* W_p   = (const float*)d_in[19];
    const float* b_p   = (const float*)d_in[20];

    float* out    = (float*)d_out;
    float* p_out  = out + OFF_P;
    float* mv_out = out + OFF_MV;
    float* w_out  = out + OFF_W;

    float *T1, *emat, *kb, *vb, *eb, *ab, *rb, *fb, *flb;
    cudaGetSymbolAddress((void**)&T1,   g_T1);
    cudaGetSymbolAddress((void**)&emat, g_emat);
    cudaGetSymbolAddress((void**)&kb,   g_k);
    cudaGetSymbolAddress((void**)&vb,   g_v);
    cudaGetSymbolAddress((void**)&eb,   g_e);
    cudaGetSymbolAddress((void**)&ab,   g_a);
    cudaGetSymbolAddress((void**)&rb,   g_read);
    cudaGetSymbolAddress((void**)&fb,   g_f);
    cudaGetSymbolAddress((void**)&flb,  g_fl);

    const int MR = BATCH * DIMS;          // 12800 rows

    gather_v_kernel<<<MR, 64>>>(q, r, v_emb, vb);
    wk_kernel<<<MR, 256>>>(q, k_emb, Mk, w_out, kb);

    // T1 = bert @ W_at^T + b_at : M=32768, N=200, K=768
    gemm_nt<0><<<dim3(4, 512), 256>>>(bert, nullptr, W_at, b_at, T1,
                                      BATCH * LBERT, DIMS, HBERT, HBERT);
    // em_at[b,i,j] = sum_l T1[b,l,i]*W_at2[j,l] + b_at2[j]
    gemm_tn_batched<<<dim3(4, 4, BATCH), 256>>>(T1, W_at2, b_at2, emat,
                                                DIMS, DIMS, LBERT);
    // e = sigmoid(v @ W_e^T + b_e), a = tanh(v @ W_a^T + b_a)
    gemm_nt<1><<<dim3(4, 200), 256>>>(vb, nullptr, W_e, b_e, eb, MR, DIMS, DIMS, DIMS);
    gemm_nt<2><<<dim3(4, 200), 256>>>(vb, nullptr, W_a, b_a, ab, MR, DIMS, DIMS, DIMS);

    scan_kernel<<<dim3(4, BATCH), 256>>>(w_out, eb, ab, Mv0, mv_out, rb);

    // f = tanh(concat(read,k) @ W_f^T + b_f)
    gemm_nt<2><<<dim3(4, 200), 256>>>(rb, kb, W_f, b_f, fb, MR, DIMS, 2 * DIMS, DIMS);
    // f_l = relu(concat(v, em_at) @ W_fus^T + b_fus)
    gemm_nt<3><<<dim3(4, 200), 256>>>(vb, emat, W_fus, b_fus, flb, MR, DIMS, 2 * DIMS, DIMS);

    p_kernel<<<MR, 128>>>(fb, flb, W_p, b_p, p_out);
}

// round 2
// speedup vs baseline: 1.3899x; 1.3899x over previous
#include <cuda_runtime.h>
#include <cstdio>

// ---------------- problem constants ----------------
#define BATCH   64
#define DIMS    200
#define SIZEM   50
#define NUMQ    10000
#define LBERT   512
#define HBERT   768

// output layout: p [B*n], Mv [B*(n+1)*m*d], w [B*n*m]
#define OFF_P   0
#define OFF_MV  (BATCH*DIMS)
#define OFF_W   (OFF_MV + BATCH*(DIMS+1)*SIZEM*DIMS)

// ---------------- scratch ----------------
__device__ float g_T1  [BATCH*DIMS*LBERT];   // T1 transposed: [B,200,512]
__device__ float g_emat[BATCH*DIMS*DIMS];
__device__ float g_k   [BATCH*DIMS*DIMS];
__device__ float g_v   [BATCH*DIMS*DIMS];
__device__ float g_e   [BATCH*DIMS*DIMS];
__device__ float g_a   [BATCH*DIMS*DIMS];
__device__ float g_read[BATCH*DIMS*DIMS];
__device__ float g_f   [BATCH*DIMS*DIMS];
__device__ float g_fl  [BATCH*DIMS*DIMS];

// ---------------- gather v rows ----------------
__global__ void gather_v_kernel(const int* __restrict__ q, const int* __restrict__ r,
                                const float* __restrict__ v_emb, float* __restrict__ vbuf)
{
    int m   = blockIdx.x;
    int tid = threadIdx.x;
    int x   = q[m] + NUMQ * r[m];
    const float4* src = (const float4*)(v_emb + (size_t)x * DIMS);
    float4*       dst = (float4*)(vbuf + (size_t)m * DIMS);
    for (int i = tid; i < DIMS/4; i += 64) dst[i] = src[i];
}

// ---------------- w = softmax(k @ Mk^T), fused k gather ----------------
__global__ void wk_kernel(const int* __restrict__ q, const float* __restrict__ k_emb,
                          const float* __restrict__ Mk,
                          float* __restrict__ wOut, float* __restrict__ kbuf)
{
    int m   = blockIdx.x;
    int tid = threadIdx.x;                 // 256
    __shared__ float krow[DIMS];
    __shared__ float part4[200];
    __shared__ float logits[SIZEM];
    __shared__ float sm_max, sm_sum;

    int qi = q[m];
    if (tid < DIMS) {
        float val = k_emb[(size_t)qi * DIMS + tid];
        krow[tid] = val;
        kbuf[(size_t)m * DIMS + tid] = val;
    }
    __syncthreads();

    if (tid < 200) {
        int s = tid >> 2, g = tid & 3;
        const float* mk = Mk + s * DIMS + g * 50;
        const float* kr = krow + g * 50;
        float acc = 0.f;
        #pragma unroll 10
        for (int kk = 0; kk < 50; ++kk) acc = fmaf(kr[kk], __ldg(&mk[kk]), acc);
        part4[tid] = acc;
    }
    __syncthreads();
    if (tid < SIZEM)
        logits[tid] = part4[4*tid] + part4[4*tid+1] + part4[4*tid+2] + part4[4*tid+3];
    __syncthreads();
    if (tid < 32) {
        float v = logits[tid];
        if (tid + 32 < SIZEM) v = fmaxf(v, logits[tid + 32]);
        #pragma unroll
        for (int o = 16; o > 0; o >>= 1) v = fmaxf(v, __shfl_xor_sync(0xffffffff, v, o));
        if (tid == 0) sm_max = v;
    }
    __syncthreads();
    if (tid < SIZEM) logits[tid] = expf(logits[tid] - sm_max);
    __syncthreads();
    if (tid < 32) {
        float v = (tid < SIZEM) ? logits[tid] : 0.f;
        if (tid + 32 < SIZEM) v += logits[tid + 32];
        #pragma unroll
        for (int o = 16; o > 0; o >>= 1) v += __shfl_xor_sync(0xffffffff, v, o);
        if (tid == 0) sm_sum = v;
    }
    __syncthreads();
    if (tid < SIZEM) wOut[(size_t)m * SIZEM + tid] = logits[tid] / sm_sum;
}

// ---------------- tuned NT SGEMM: 128x40x8 tile, 8x5 microtile, 128 thr ----------------
// MODE: 0 none, 1 sigmoid, 2 tanh, 3 relu, 4 transposed-C (no act), 5 dual(e:sig, a:tanh)
// Requires: M%128==0, N%40==0, K%8==0, Ksplit%8==0. No bounds checks.
template<int MODE>
__global__ __launch_bounds__(128)
void gemm40(const float* __restrict__ A, const float* __restrict__ A2,
            const float* __restrict__ Wp, const float* __restrict__ Wp2,
            const float* __restrict__ biasp, const float* __restrict__ bias2,
            float* __restrict__ C, float* __restrict__ C2,
            int K, int Ksplit, int Nout)
{
    __shared__ float As[2][8][128];
    __shared__ float Ws[2][8][40];
    const int tid = threadIdx.x;
    const int bm = blockIdx.y * 128;
    int bn = blockIdx.x * 40;

    const float* W = Wp; const float* bs = biasp; float* Co = C;
    bool second = false;
    if (MODE == 5 && bn >= 200) { W = Wp2; bs = bias2; Co = C2; bn -= 200; second = true; }

    const int tng = tid & 7;
    const int tm  = (tid >> 3) * 8;
    const int K2  = K - Ksplit;

    const float* Arow  = A  + (size_t)(bm + tid) * Ksplit;
    const float* A2row = (A2 != nullptr) ? A2 + (size_t)(bm + tid) * K2 : nullptr;
    const float* Wrow  = W + (size_t)(bn + tid) * K;   // only valid for tid<40

    float acc[8][5] = {};
    float4 a0, a1, w0 = {0,0,0,0}, w1 = {0,0,0,0};

    // prefetch k0 = 0
    a0 = *(const float4*)Arow;
    a1 = *(const float4*)(Arow + 4);
    if (tid < 40) { w0 = *(const float4*)Wrow; w1 = *(const float4*)(Wrow + 4); }

    const int nIter = K >> 3;
    int cur = 0;
    As[0][0][tid] = a0.x; As[0][1][tid] = a0.y; As[0][2][tid] = a0.z; As[0][3][tid] = a0.w;
    As[0][4][tid] = a1.x; As[0][5][tid] = a1.y; As[0][6][tid] = a1.z; As[0][7][tid] = a1.w;
    if (tid < 40) {
        Ws[0][0][tid] = w0.x; Ws[0][1][tid] = w0.y; Ws[0][2][tid] = w0.z; Ws[0][3][tid] = w0.w;
        Ws[0][4][tid] = w1.x; Ws[0][5][tid] = w1.y; Ws[0][6][tid] = w1.z; Ws[0][7][tid] = w1.w;
    }
    __syncthreads();

    for (int it = 0; it < nIter; ++it) {
        if (it + 1 < nIter) {
            int kg = (it + 1) * 8;
            const float* s = (kg < Ksplit) ? Arow + kg : A2row + (kg - Ksplit);
            a0 = *(const float4*)s; a1 = *(const float4*)(s + 4);
            if (tid < 40) { w0 = *(const float4*)(Wrow + kg); w1 = *(const float4*)(Wrow + kg + 4); }
        }
        #pragma unroll
        for (int kk = 0; kk < 8; ++kk) {
            float4 x0 = *(const float4*)&As[cur][kk][tm];
            float4 x1 = *(const float4*)&As[cur][kk][tm + 4];
            float xa[8] = {x0.x, x0.y, x0.z, x0.w, x1.x, x1.y, x1.z, x1.w};
            float wv[5];
            #pragma unroll
            for (int jj = 0; jj < 5; ++jj) wv[jj] = Ws[cur][kk][tng + 8 * jj];
            #pragma unroll
            for (int i = 0; i < 8; ++i)
                #pragma unroll
                for (int jj = 0; jj < 5; ++jj)
                    acc[i][jj] = fmaf(xa[i], wv[jj], acc[i][jj]);
        }
        if (it + 1 < nIter) {
            int nx = cur ^ 1;
            As[nx][0][tid] = a0.x; As[nx][1][tid] = a0.y; As[nx][2][tid] = a0.z; As[nx][3][tid] = a0.w;
            As[nx][4][tid] = a1.x; As[nx][5][tid] = a1.y; As[nx][6][tid] = a1.z; As[nx][7][tid] = a1.w;
            if (tid < 40) {
                Ws[nx][0][tid] = w0.x; Ws[nx][1][tid] = w0.y; Ws[nx][2][tid] = w0.z; Ws[nx][3][tid] = w0.w;
                Ws[nx][4][tid] = w1.x; Ws[nx][5][tid] = w1.y; Ws[nx][6][tid] = w1.z; Ws[nx][7][tid] = w1.w;
            }
        }
        __syncthreads();
        cur ^= 1;
    }

    if (MODE == 4) {
        // transposed store: m = b*512 + l, write C[b, n, l] (contiguous in l)
        int b  = bm >> 9;
        int l0 = bm & 511;
        #pragma unroll
        for (int jj = 0; jj < 5; ++jj) {
            int n = bn + tng + 8 * jj;
            float bb = bs[n];
            float* base = Co + ((size_t)b * 200 + n) * 512 + l0 + tm;
            float4 o0 = {acc[0][jj] + bb, acc[1][jj] + bb, acc[2][jj] + bb, acc[3][jj] + bb};
            float4 o1 = {acc[4][jj] + bb, acc[5][jj] + bb, acc[6][jj] + bb, acc[7][jj] + bb};
            *(float4*)base = o0;
            *(float4*)(base + 4) = o1;
        }
    } else {
        #pragma unroll
        for (int jj = 0; jj < 5; ++jj) {
            int n = bn + tng + 8 * jj;
            float bb = bs[n];
            #pragma unroll
            for (int i = 0; i < 8; ++i) {
                float v = acc[i][jj] + bb;
                if (MODE == 1) v = 1.f / (1.f + expf(-v));
                else if (MODE == 2) v = tanhf(v);
                else if (MODE == 3) v = fmaxf(v, 0.f);
                else if (MODE == 5) v = second ? tanhf(v) : 1.f / (1.f + expf(-v));
                Co[(size_t)(bm + tm + i) * Nout + n] = v;
            }
        }
    }
}

// ---------------- memory scan ----------------
// grid (8 j-chunks of 25, 64 batches), 256 threads, 2 syncs/iter
__global__ void scan_kernel(const float* __restrict__ w,     // [B,200,50]
                            const float* __restrict__ e,     // [B,200,200]
                            const float* __restrict__ a,     // [B,200,200]
                            const float* __restrict__ Mv0,   // [50,200]
                            float* __restrict__ MvOut,       // [B,201,50,200]
                            float* __restrict__ readOut)     // [B,200,200]
{
    const int cs = blockIdx.x;            // 0..7
    const int b  = blockIdx.y;
    const int j0 = cs * 25;
    __shared__ float Mv_s[SIZEM * 25];    // [s][j]
    __shared__ float w_s[SIZEM], e_s[25], a_s[25];
    __shared__ float part[8 * 25];
    const int tid = threadIdx.x;

    for (int idx = tid; idx < SIZEM * 25; idx += 256) {
        int s = idx / 25, j = idx % 25;
        Mv_s[idx] = Mv0[s * DIMS + j0 + j];
    }

    const int sg = tid / 25;              // 0..7 for tid<200
    const int j  = tid % 25;
    const int cnt = 6 + (sg < 2 ? 1 : 0);
    const int sst = sg * 6 + min(sg, 2);

    // prefetch t=0
    float r_w = 0.f, r_e = 0.f, r_a = 0.f;
    if (tid < SIZEM) r_w = w[(size_t)b * DIMS * SIZEM + tid];
    if (tid < 25) {
        r_e = e[(size_t)b * DIMS * DIMS + j0 + tid];
        r_a = a[(size_t)b * DIMS * DIMS + j0 + tid];
    }
    __syncthreads();

    for (int t = 0; t < DIMS; ++t) {
        if (tid < SIZEM) w_s[tid] = r_w;
        if (tid < 25) { e_s[tid] = r_e; a_s[tid] = r_a; }
        if (t > 0 && tid >= 200 && tid < 225) {
            int j2 = tid - 200;
            float s0 = part[j2] + part[25 + j2] + part[50 + j2] + part[75 + j2]
                     + part[100 + j2] + part[125 + j2] + part[150 + j2] + part[175 + j2];
            readOut[((size_t)b * DIMS + (t - 1)) * DIMS + j0 + j2] = s0;
        }
        __syncthreads();

        // prefetch t+1
        if (t + 1 < DIMS) {
            if (tid < SIZEM) r_w = w[((size_t)b * DIMS + t + 1) * SIZEM + tid];
            if (tid < 25) {
                r_e = e[((size_t)b * DIMS + t + 1) * DIMS + j0 + tid];
                r_a = a[((size_t)b * DIMS + t + 1) * DIMS + j0 + tid];
            }
        }

        if (tid < 200) {
            float accum = 0.f;
            float ej = e_s[j], aj = a_s[j];
            float* outb = MvOut + ((size_t)(b * (DIMS + 1) + t) * SIZEM) * DIMS + j0 + j;
            #pragma unroll 7
            for (int s = sst; s < sst + cnt; ++s) {
                float m  = Mv_s[s * 25 + j];
                float wv = w_s[s];
                outb[(size_t)s * DIMS] = m;                       // emit pre-update
                accum = fmaf(wv, m, accum);
                Mv_s[s * 25 + j] = fmaf(wv, fmaf(-ej, m, aj), m); // m + w*(a - e*m)
            }
            part[sg * 25 + j] = accum;
        }
        __syncthreads();
    }

    // finalize read[199]
    if (tid >= 200 && tid < 225) {
        int j2 = tid - 200;
        float s0 = part[j2] + part[25 + j2] + part[50 + j2] + part[75 + j2]
                 + part[100 + j2] + part[125 + j2] + part[150 + j2] + part[175 + j2];
        readOut[((size_t)b * DIMS + 199) * DIMS + j0 + j2] = s0;
    }
    // emit final state (t = 200)
    for (int idx = tid; idx < SIZEM * 25; idx += 256) {
        int s = idx / 25, jj = idx % 25;
        MvOut[((size_t)(b * (DIMS + 1) + DIMS) * SIZEM + s) * DIMS + j0 + jj] = Mv_s[idx];
    }
}

// ---------------- final p ----------------
__global__ void p_kernel(const float* __restrict__ f, const float* __restrict__ fl,
                         const float* __restrict__ Wp, const float* __restrict__ bp,
                         float* __restrict__ pOut)
{
    int bt = blockIdx.x;
    int b  = bt / DIMS, t = bt % DIMS;
    int tid = threadIdx.x;                // 128
    float acc = 0.f;
    for (int c = tid; c < 2 * DIMS; c += 128) {
        float xv = (c < DIMS) ? f[(size_t)bt * DIMS + c]
                              : fl[((size_t)b * DIMS + (c - DIMS)) * DIMS + t];
        acc = fmaf(Wp[c], xv, acc);
    }
    __shared__ float red[128];
    red[tid] = acc;
    __syncthreads();
    #pragma unroll
    for (int s = 64; s > 0; s >>= 1) {
        if (tid < s) red[tid] += red[tid + s];
        __syncthreads();
    }
    if (tid == 0) pOut[bt] = 1.f / (1.f + expf(-(red[0] + bp[0])));
}

// ---------------- launcher ----------------
extern "C" void kernel_launch(void* const* d_in, const int* in_sizes, int n_in,
                              void* d_out, int out_size)
{
    const int*   q     = (const int*)d_in[0];
    const int*   r     = (const int*)d_in[1];
    const float* bert  = (const float*)d_in[2];
    const float* k_emb = (const float*)d_in[3];
    const float* v_emb = (const float*)d_in[4];
    const float* Mk    = (const float*)d_in[5];
    const float* Mv0   = (const float*)d_in[6];
    const float* W_at  = (const float*)d_in[7];
    const float* b_at  = (const float*)d_in[8];
    const float* W_at2 = (const float*)d_in[9];
    const float* b_at2 = (const float*)d_in[10];
    const float* W_fus = (const float*)d_in[11];
    const float* b_fus = (const float*)d_in[12];
    const float* W_e   = (const float*)d_in[13];
    const float* b_e   = (const float*)d_in[14];
    const float* W_a   = (const float*)d_in[15];
    const float* b_a   = (const float*)d_in[16];
    const float* W_f   = (const float*)d_in[17];
    const float* b_f   = (const float*)d_in[18];
    const float* W_p   = (const float*)d_in[19];
    const float* b_p   = (const float*)d_in[20];

    float* out    = (float*)d_out;
    float* p_out  = out + OFF_P;
    float* mv_out = out + OFF_MV;
    float* w_out  = out + OFF_W;

    float *T1, *emat, *kb, *vb, *eb, *ab, *rb, *fb, *flb;
    cudaGetSymbolAddress((void**)&T1,   g_T1);
    cudaGetSymbolAddress((void**)&emat, g_emat);
    cudaGetSymbolAddress((void**)&kb,   g_k);
    cudaGetSymbolAddress((void**)&vb,   g_v);
    cudaGetSymbolAddress((void**)&eb,   g_e);
    cudaGetSymbolAddress((void**)&ab,   g_a);
    cudaGetSymbolAddress((void**)&rb,   g_read);
    cudaGetSymbolAddress((void**)&fb,   g_f);
    cudaGetSymbolAddress((void**)&flb,  g_fl);

    const int MR = BATCH * DIMS;          // 12800

    gather_v_kernel<<<MR, 64>>>(q, r, v_emb, vb);
    wk_kernel<<<MR, 256>>>(q, k_emb, Mk, w_out, kb);

    // T1t[b,i,l] = (bert @ W_at^T + b_at) transposed : M=32768, N=200, K=768
    gemm40<4><<<dim3(5, 256), 128>>>(bert, nullptr, W_at, nullptr, b_at, nullptr,
                                     T1, nullptr, HBERT, HBERT, 0);
    // em_at = T1t @ W_at2^T + b_at2 : M=12800, N=200, K=512
    gemm40<0><<<dim3(5, 100), 128>>>(T1, nullptr, W_at2, nullptr, b_at2, nullptr,
                                     emat, nullptr, LBERT, LBERT, DIMS);
    // e = sigmoid(v@W_e^T+b_e), a = tanh(v@W_a^T+b_a) : fused dual, N=400
    gemm40<5><<<dim3(10, 100), 128>>>(vb, nullptr, W_e, W_a, b_e, b_a,
                                      eb, ab, DIMS, DIMS, DIMS);

    scan_kernel<<<dim3(8, BATCH), 256>>>(w_out, eb, ab, Mv0, mv_out, rb);

    // f = tanh(concat(read,k) @ W_f^T + b_f) : K=400
    gemm40<2><<<dim3(5, 100), 128>>>(rb, kb, W_f, nullptr, b_f, nullptr,
                                     fb, nullptr, 2 * DIMS, DIMS, DIMS);
    // f_l = relu(concat(v, em_at) @ W_fus^T + b_fus) : K=400
    gemm40<3><<<dim3(5, 100), 128>>>(vb, emat, W_fus, nullptr, b_fus, nullptr,
                                     flb, nullptr, 2 * DIMS, DIMS, DIMS);

    p_kernel<<<MR, 128>>>(fb, flb, W_p, b_p, p_out);
}

// round 4
// speedup vs baseline: 2.0181x; 1.4520x over previous
#include <cuda_runtime.h>
#include <cuda_bf16.h>
#include <cstdint>
#include <cstdio>

// ---------------- problem constants ----------------
#define BATCH   64
#define DIMS    200
#define SIZEM   50
#define NUMQ    10000
#define LBERT   512
#define HBERT   768

#define OFF_P   0
#define OFF_MV  (BATCH*DIMS)
#define OFF_W   (OFF_MV + BATCH*(DIMS+1)*SIZEM*DIMS)

// ---------------- scratch ----------------
__device__ float g_T1  [BATCH*DIMS*LBERT];   // T1 transposed: [B,200,512]
__device__ float g_emat[BATCH*DIMS*DIMS];
__device__ float g_k   [BATCH*DIMS*DIMS];
__device__ float g_v   [BATCH*DIMS*DIMS];
__device__ float g_e   [BATCH*DIMS*DIMS];
__device__ float g_a   [BATCH*DIMS*DIMS];
__device__ float g_read[BATCH*DIMS*DIMS];
__device__ float g_f   [BATCH*DIMS*DIMS];
__device__ float g_fl  [BATCH*DIMS*DIMS];

// ================= low-level helpers =================
__device__ __forceinline__ void cp16(uint32_t saddr, const void* g) {
    asm volatile("cp.async.cg.shared.global [%0], [%1], 16;" :: "r"(saddr), "l"(g));
}
#define CP_COMMIT asm volatile("cp.async.commit_group;" ::: "memory")
#define CP_WAIT0  asm volatile("cp.async.wait_group 0;" ::: "memory")

__device__ __forceinline__ void mma16816(float* c, const uint32_t* a, uint32_t b0, uint32_t b1) {
    asm volatile("mma.sync.aligned.m16n8k16.row.col.f32.bf16.bf16.f32 "
        "{%0,%1,%2,%3}, {%4,%5,%6,%7}, {%8,%9}, {%0,%1,%2,%3};"
        : "+f"(c[0]), "+f"(c[1]), "+f"(c[2]), "+f"(c[3])
        : "r"(a[0]), "r"(a[1]), "r"(a[2]), "r"(a[3]), "r"(b0), "r"(b1));
}

__device__ __forceinline__ void split2(float x, float y, uint32_t& hi, uint32_t& lo) {
    __nv_bfloat16 hx = __float2bfloat16(x), hy = __float2bfloat16(y);
    float rx = x - __bfloat162float(hx), ry = y - __bfloat162float(hy);
    __nv_bfloat16 lx = __float2bfloat16(rx), ly = __float2bfloat16(ry);
    hi = (uint32_t)__bfloat16_as_ushort(hx) | ((uint32_t)__bfloat16_as_ushort(hy) << 16);
    lo = (uint32_t)__bfloat16_as_ushort(lx) | ((uint32_t)__bfloat16_as_ushort(ly) << 16);
}

// ================= mma.sync bf16-split SGEMM =================
// Block: 256 thr (8 warps). Tile: M=128 (warp=16 rows), N=200 (25 n-frags), K-chunk 32.
// smem layout (bytes):
#define SA_STRIDE 40                         // fp32 elems per A row (32 used)
#define SB_STRIDE 20                         // u32 elems per B bf16-pair row (16 used)
#define SM_BIAS   0                          // 800 B
#define SM_AFP    1024                       // 2 * 128*40*4 = 40960
#define SM_BFP    (SM_AFP + 2*128*SA_STRIDE*4)        // 2 * 200*32*4 = 51200
#define SM_BHI    (SM_BFP + 2*200*32*4)               // 200*20*4 = 16000
#define SM_BLO    (SM_BHI + 200*SB_STRIDE*4)          // 16000
#define GEMM_SMEM (SM_BLO + 200*SB_STRIDE*4)          // 125184

__device__ __forceinline__ void load_tileA(const float* __restrict__ A,
                                           const float* __restrict__ A2,
                                           int K, int Ksplit, int bm, int kstart,
                                           float* Afp, int tid)
{
    int kend = kstart + 32;
    bool s1 = (kend <= Ksplit);
    bool s2 = (kstart >= Ksplit) && (kend <= K);
    if (s1 || s2) {
        const float* base = s1 ? (A + (size_t)bm * Ksplit + kstart)
                               : (A2 + (size_t)bm * (K - Ksplit) + (kstart - Ksplit));
        size_t rs = s1 ? (size_t)Ksplit : (size_t)(K - Ksplit);
        uint32_t sb = (uint32_t)__cvta_generic_to_shared(Afp);
        #pragma unroll
        for (int pass = 0; pass < 4; ++pass) {
            int idx = tid + pass * 256;           // 1024 chunks of 16B
            int row = idx >> 3, c4 = idx & 7;
            cp16(sb + (uint32_t)(row * SA_STRIDE + c4 * 4) * 4, base + (size_t)row * rs + c4 * 4);
        }
    } else {
        int K2 = K - Ksplit;
        for (int idx = tid; idx < 4096; idx += 256) {
            int row = idx >> 5, kk = idx & 31;
            int k = kstart + kk;
            float v = 0.f;
            if (k < K) v = (k < Ksplit) ? A[(size_t)(bm + row) * Ksplit + k]
                                        : A2[(size_t)(bm + row) * K2 + (k - Ksplit)];
            Afp[row * SA_STRIDE + kk] = v;
        }
    }
}

__device__ __forceinline__ void load_tileB(const float* __restrict__ W, int K, int kstart,
                                           float* Bfp, int tid)
{
    if (kstart + 32 <= K) {
        uint32_t sb = (uint32_t)__cvta_generic_to_shared(Bfp);
        for (int idx = tid; idx < 1600; idx += 256) {
            int row = idx >> 3, c4 = idx & 7;
            cp16(sb + (uint32_t)(row * 32 + c4 * 4) * 4, W + (size_t)row * K + kstart + c4 * 4);
        }
    } else {
        for (int idx = tid; idx < 6400; idx += 256) {
            int row = idx >> 5, kk = idx & 31;
            int k = kstart + kk;
            Bfp[row * 32 + kk] = (k < K) ? W[(size_t)row * K + k] : 0.f;
        }
    }
}

__device__ __forceinline__ void convertB(const float* __restrict__ Bfp,
                                         uint32_t* __restrict__ Bhi,
                                         uint32_t* __restrict__ Blo, int tid)
{
    for (int idx = tid; idx < 3200; idx += 256) {
        int n = idx >> 4, kp = idx & 15;
        float2 v = *(const float2*)&Bfp[n * 32 + kp * 2];
        uint32_t h, l;
        split2(v.x, v.y, h, l);
        Bhi[n * SB_STRIDE + kp] = h;
        Blo[n * SB_STRIDE + kp] = l;
    }
}

// MODE: 0 none, 1 sigmoid, 2 tanh, 3 relu, 4 transposed-T1 store, 5 dual (sig | tanh)
template<int MODE>
__global__ void __launch_bounds__(256)
tgemm(const float* __restrict__ A, const float* __restrict__ A2,
      const float* __restrict__ Wa, const float* __restrict__ Wb,
      const float* __restrict__ biasa, const float* __restrict__ biasb,
      float* __restrict__ Ca, float* __restrict__ Cb,
      int K, int Ksplit)
{
    extern __shared__ char smem[];
    float*    biasS = (float*)(smem + SM_BIAS);
    float*    Afp[2] = { (float*)(smem + SM_AFP), (float*)(smem + SM_AFP) + 128 * SA_STRIDE };
    float*    Bfp[2] = { (float*)(smem + SM_BFP), (float*)(smem + SM_BFP) + 200 * 32 };
    uint32_t* Bhi = (uint32_t*)(smem + SM_BHI);
    uint32_t* Blo = (uint32_t*)(smem + SM_BLO);

    const int tid  = threadIdx.x;
    const int wid  = tid >> 5;
    const int lane = tid & 31;
    const int gid  = lane >> 2;
    const int tig  = lane & 3;
    const int warpM = wid * 16;

    const float* W  = Wa;
    const float* bs = biasa;
    float* C = Ca;
    bool second = false;
    int bx = blockIdx.x;
    if (MODE == 5) {
        int half = gridDim.x >> 1;
        if (bx >= half) { W = Wb; bs = biasb; C = Cb; second = true; bx -= half; }
    }
    const int bm = bx * 128;

    for (int i = tid; i < 200; i += 256) biasS[i] = bs[i];

    const int NC = (K + 31) >> 5;

    // chunk 0
    load_tileA(A, A2, K, Ksplit, bm, 0, Afp[0], tid);
    load_tileB(W, K, 0, Bfp[0], tid);
    CP_COMMIT;
    CP_WAIT0;
    __syncthreads();
    convertB(Bfp[0], Bhi, Blo, tid);
    __syncthreads();

    float c[25][4];
    #pragma unroll
    for (int i = 0; i < 25; ++i) { c[i][0] = 0.f; c[i][1] = 0.f; c[i][2] = 0.f; c[i][3] = 0.f; }

    for (int ch = 0; ch < NC; ++ch) {
        const float* Acur = Afp[ch & 1];
        if (ch + 1 < NC) {
            load_tileA(A, A2, K, Ksplit, bm, (ch + 1) * 32, Afp[(ch + 1) & 1], tid);
            load_tileB(W, K, (ch + 1) * 32, Bfp[(ch + 1) & 1], tid);
            CP_COMMIT;
        }
        #pragma unroll
        for (int st = 0; st < 2; ++st) {
            const int koff = st * 16;
            uint32_t ah[4], al[4];
            #pragma unroll
            for (int i = 0; i < 4; ++i) {
                int rr = warpM + gid + (i & 1) * 8;
                int kk = koff + 2 * tig + ((i >> 1) * 8);
                float2 v = *(const float2*)&Acur[rr * SA_STRIDE + kk];
                split2(v.x, v.y, ah[i], al[i]);
            }
            const int bw = koff >> 1;     // word offset within B row
            #pragma unroll
            for (int nf = 0; nf < 25; ++nf) {
                int n = nf * 8 + gid;
                uint32_t bh0 = Bhi[n * SB_STRIDE + bw + tig];
                uint32_t bh1 = Bhi[n * SB_STRIDE + bw + tig + 4];
                uint32_t bl0 = Blo[n * SB_STRIDE + bw + tig];
                uint32_t bl1 = Blo[n * SB_STRIDE + bw + tig + 4];
                mma16816(c[nf], ah, bh0, bh1);
                mma16816(c[nf], ah, bl0, bl1);
                mma16816(c[nf], al, bh0, bh1);
            }
        }
        if (ch + 1 < NC) {
            CP_WAIT0;
            __syncthreads();
            convertB(Bfp[(ch + 1) & 1], Bhi, Blo, tid);
            __syncthreads();
        }
    }

    // ---------------- epilogue ----------------
    const int m0 = bm + warpM + gid;
    #pragma unroll
    for (int nf = 0; nf < 25; ++nf) {
        int n = nf * 8 + 2 * tig;
        float b0v = biasS[n], b1v = biasS[n + 1];
        float v00 = c[nf][0] + b0v, v01 = c[nf][1] + b1v;
        float v10 = c[nf][2] + b0v, v11 = c[nf][3] + b1v;
        if (MODE == 1) {
            v00 = 1.f / (1.f + expf(-v00)); v01 = 1.f / (1.f + expf(-v01));
            v10 = 1.f / (1.f + expf(-v10)); v11 = 1.f / (1.f + expf(-v11));
        } else if (MODE == 2) {
            v00 = tanhf(v00); v01 = tanhf(v01); v10 = tanhf(v10); v11 = tanhf(v11);
        } else if (MODE == 3) {
            v00 = fmaxf(v00, 0.f); v01 = fmaxf(v01, 0.f);
            v10 = fmaxf(v10, 0.f); v11 = fmaxf(v11, 0.f);
        } else if (MODE == 5) {
            if (second) { v00 = tanhf(v00); v01 = tanhf(v01); v10 = tanhf(v10); v11 = tanhf(v11); }
            else {
                v00 = 1.f / (1.f + expf(-v00)); v01 = 1.f / (1.f + expf(-v01));
                v10 = 1.f / (1.f + expf(-v10)); v11 = 1.f / (1.f + expf(-v11));
            }
        }
        if (MODE == 4) {
            int b = bm >> 9;
            int l = (bm & 511) + warpM + gid;
            float* base = C + ((size_t)b * 200 + n) * 512;
            base[l] = v00;
            base[512 + l] = v01;
            base[l + 8] = v10;
            base[512 + l + 8] = v11;
        } else {
            float2 lo2 = {v00, v01}, hi2 = {v10, v11};
            *(float2*)&C[(size_t)m0 * 200 + n] = lo2;
            *(float2*)&C[(size_t)(m0 + 8) * 200 + n] = hi2;
        }
    }
}

// ---------------- gather v rows ----------------
__global__ void gather_v_kernel(const int* __restrict__ q, const int* __restrict__ r,
                                const float* __restrict__ v_emb, float* __restrict__ vbuf)
{
    int m   = blockIdx.x;
    int tid = threadIdx.x;
    int x   = q[m] + NUMQ * r[m];
    const float4* src = (const float4*)(v_emb + (size_t)x * DIMS);
    float4*       dst = (float4*)(vbuf + (size_t)m * DIMS);
    for (int i = tid; i < DIMS / 4; i += 64) dst[i] = src[i];
}

// ---------------- w = softmax(k @ Mk^T), fused k gather ----------------
__global__ void wk_kernel(const int* __restrict__ q, const float* __restrict__ k_emb,
                          const float* __restrict__ Mk,
                          float* __restrict__ wOut, float* __restrict__ kbuf)
{
    int m   = blockIdx.x;
    int tid = threadIdx.x;                 // 256
    __shared__ float krow[DIMS];
    __shared__ float part4[200];
    __shared__ float logits[SIZEM];
    __shared__ float sm_max, sm_sum;

    int qi = q[m];
    if (tid < DIMS) {
        float val = k_emb[(size_t)qi * DIMS + tid];
        krow[tid] = val;
        kbuf[(size_t)m * DIMS + tid] = val;
    }
    __syncthreads();

    if (tid < 200) {
        int s = tid >> 2, g = tid & 3;
        const float* mk = Mk + s * DIMS + g * 50;
        const float* kr = krow + g * 50;
        float acc = 0.f;
        #pragma unroll 10
        for (int kk = 0; kk < 50; ++kk) acc = fmaf(kr[kk], __ldg(&mk[kk]), acc);
        part4[tid] = acc;
    }
    __syncthreads();
    if (tid < SIZEM)
        logits[tid] = part4[4 * tid] + part4[4 * tid + 1] + part4[4 * tid + 2] + part4[4 * tid + 3];
    __syncthreads();
    if (tid < 32) {
        float v = logits[tid];
        if (tid + 32 < SIZEM) v = fmaxf(v, logits[tid + 32]);
        #pragma unroll
        for (int o = 16; o > 0; o >>= 1) v = fmaxf(v, __shfl_xor_sync(0xffffffff, v, o));
        if (tid == 0) sm_max = v;
    }
    __syncthreads();
    if (tid < SIZEM) logits[tid] = expf(logits[tid] - sm_max);
    __syncthreads();
    if (tid < 32) {
        float v = (tid < SIZEM) ? logits[tid] : 0.f;
        if (tid + 32 < SIZEM) v += logits[tid + 32];
        #pragma unroll
        for (int o = 16; o > 0; o >>= 1) v += __shfl_xor_sync(0xffffffff, v, o);
        if (tid == 0) sm_sum = v;
    }
    __syncthreads();
    if (tid < SIZEM) wOut[(size_t)m * SIZEM + tid] = logits[tid] / sm_sum;
}

// ---------------- memory scan ----------------
__global__ void scan_kernel(const float* __restrict__ w,
                            const float* __restrict__ e,
                            const float* __restrict__ a,
                            const float* __restrict__ Mv0,
                            float* __restrict__ MvOut,
                            float* __restrict__ readOut)
{
    const int cs = blockIdx.x;            // 0..7
    const int b  = blockIdx.y;
    const int j0 = cs * 25;
    __shared__ float Mv_s[SIZEM * 25];
    __shared__ float w_s[SIZEM], e_s[25], a_s[25];
    __shared__ float part[8 * 25];
    const int tid = threadIdx.x;

    for (int idx = tid; idx < SIZEM * 25; idx += 256) {
        int s = idx / 25, j = idx % 25;
        Mv_s[idx] = Mv0[s * DIMS + j0 + j];
    }

    const int sg = tid / 25;
    const int j  = tid % 25;
    const int cnt = 6 + (sg < 2 ? 1 : 0);
    const int sst = sg * 6 + min(sg, 2);

    float r_w = 0.f, r_e = 0.f, r_a = 0.f;
    if (tid < SIZEM) r_w = w[(size_t)b * DIMS * SIZEM + tid];
    if (tid < 25) {
        r_e = e[(size_t)b * DIMS * DIMS + j0 + tid];
        r_a = a[(size_t)b * DIMS * DIMS + j0 + tid];
    }
    __syncthreads();

    for (int t = 0; t < DIMS; ++t) {
        if (tid < SIZEM) w_s[tid] = r_w;
        if (tid < 25) { e_s[tid] = r_e; a_s[tid] = r_a; }
        if (t > 0 && tid >= 200 && tid < 225) {
            int j2 = tid - 200;
            float s0 = part[j2] + part[25 + j2] + part[50 + j2] + part[75 + j2]
                     + part[100 + j2] + part[125 + j2] + part[150 + j2] + part[175 + j2];
            readOut[((size_t)b * DIMS + (t - 1)) * DIMS + j0 + j2] = s0;
        }
        __syncthreads();

        if (t + 1 < DIMS) {
            if (tid < SIZEM) r_w = w[((size_t)b * DIMS + t + 1) * SIZEM + tid];
            if (tid < 25) {
                r_e = e[((size_t)b * DIMS + t + 1) * DIMS + j0 + tid];
                r_a = a[((size_t)b * DIMS + t + 1) * DIMS + j0 + tid];
            }
        }

        if (tid < 200) {
            float accum = 0.f;
            float ej = e_s[j], aj = a_s[j];
            float* outb = MvOut + ((size_t)(b * (DIMS + 1) + t) * SIZEM) * DIMS + j0 + j;
            #pragma unroll 7
            for (int s = sst; s < sst + cnt; ++s) {
                float m  = Mv_s[s * 25 + j];
                float wv = w_s[s];
                outb[(size_t)s * DIMS] = m;
                accum = fmaf(wv, m, accum);
                Mv_s[s * 25 + j] = fmaf(wv, fmaf(-ej, m, aj), m);
            }
            part[sg * 25 + j] = accum;
        }
        __syncthreads();
    }

    if (tid >= 200 && tid < 225) {
        int j2 = tid - 200;
        float s0 = part[j2] + part[25 + j2] + part[50 + j2] + part[75 + j2]
                 + part[100 + j2] + part[125 + j2] + part[150 + j2] + part[175 + j2];
        readOut[((size_t)b * DIMS + 199) * DIMS + j0 + j2] = s0;
    }
    for (int idx = tid; idx < SIZEM * 25; idx += 256) {
        int s = idx / 25, jj = idx % 25;
        MvOut[((size_t)(b * (DIMS + 1) + DIMS) * SIZEM + s) * DIMS + j0 + jj] = Mv_s[idx];
    }
}

// ---------------- final p ----------------
__global__ void p_kernel(const float* __restrict__ f, const float* __restrict__ fl,
                         const float* __restrict__ Wp, const float* __restrict__ bp,
                         float* __restrict__ pOut)
{
    int bt = blockIdx.x;
    int b  = bt / DIMS, t = bt % DIMS;
    int tid = threadIdx.x;                // 128
    float acc = 0.f;
    for (int c = tid; c < 2 * DIMS; c += 128) {
        float xv = (c < DIMS) ? f[(size_t)bt * DIMS + c]
                              : fl[((size_t)b * DIMS + (c - DIMS)) * DIMS + t];
        acc = fmaf(Wp[c], xv, acc);
    }
    __shared__ float red[128];
    red[tid] = acc;
    __syncthreads();
    #pragma unroll
    for (int s = 64; s > 0; s >>= 1) {
        if (tid < s) red[tid] += red[tid + s];
        __syncthreads();
    }
    if (tid == 0) pOut[bt] = 1.f / (1.f + expf(-(red[0] + bp[0])));
}

// ---------------- launcher ----------------
extern "C" void kernel_launch(void* const* d_in, const int* in_sizes, int n_in,
                              void* d_out, int out_size)
{
    const int*   q     = (const int*)d_in[0];
    const int*   r     = (const int*)d_in[1];
    const float* bert  = (const float*)d_in[2];
    const float* k_emb = (const float*)d_in[3];
    const float* v_emb = (const float*)d_in[4];
    const float* Mk    = (const float*)d_in[5];
    const float* Mv0   = (const float*)d_in[6];
    const float* W_at  = (const float*)d_in[7];
    const float* b_at  = (const float*)d_in[8];
    const float* W_at2 = (const float*)d_in[9];
    const float* b_at2 = (const float*)d_in[10];
    const float* W_fus = (const float*)d_in[11];
    const float* b_fus = (const float*)d_in[12];
    const float* W_e   = (const float*)d_in[13];
    const float* b_e   = (const float*)d_in[14];
    const float* W_a   = (const float*)d_in[15];
    const float* b_a   = (const float*)d_in[16];
    const float* W_f   = (const float*)d_in[17];
    const float* b_f   = (const float*)d_in[18];
    const float* W_p   = (const float*)d_in[19];
    const float* b_p   = (const float*)d_in[20];

    float* out    = (float*)d_out;
    float* p_out  = out + OFF_P;
    float* mv_out = out + OFF_MV;
    float* w_out  = out + OFF_W;

    float *T1, *emat, *kb, *vb, *eb, *ab, *rb, *fb, *flb;
    cudaGetSymbolAddress((void**)&T1,   g_T1);
    cudaGetSymbolAddress((void**)&emat, g_emat);
    cudaGetSymbolAddress((void**)&kb,   g_k);
    cudaGetSymbolAddress((void**)&vb,   g_v);
    cudaGetSymbolAddress((void**)&eb,   g_e);
    cudaGetSymbolAddress((void**)&ab,   g_a);
    cudaGetSymbolAddress((void**)&rb,   g_read);
    cudaGetSymbolAddress((void**)&fb,   g_f);
    cudaGetSymbolAddress((void**)&flb,  g_fl);

    cudaFuncSetAttribute(tgemm<0>, cudaFuncAttributeMaxDynamicSharedMemorySize, GEMM_SMEM);
    cudaFuncSetAttribute(tgemm<2>, cudaFuncAttributeMaxDynamicSharedMemorySize, GEMM_SMEM);
    cudaFuncSetAttribute(tgemm<3>, cudaFuncAttributeMaxDynamicSharedMemorySize, GEMM_SMEM);
    cudaFuncSetAttribute(tgemm<4>, cudaFuncAttributeMaxDynamicSharedMemorySize, GEMM_SMEM);
    cudaFuncSetAttribute(tgemm<5>, cudaFuncAttributeMaxDynamicSharedMemorySize, GEMM_SMEM);

    const int MR = BATCH * DIMS;          // 12800

    gather_v_kernel<<<MR, 64>>>(q, r, v_emb, vb);
    wk_kernel<<<MR, 256>>>(q, k_emb, Mk, w_out, kb);

    // T1t[b,i,l] = (bert @ W_at^T + b_at)^T : M=32768, K=768
    tgemm<4><<<256, 256, GEMM_SMEM>>>(bert, nullptr, W_at, nullptr, b_at, nullptr,
                                      T1, nullptr, HBERT, HBERT);
    // em_at = T1t @ W_at2^T + b_at2 : M=12800, K=512
    tgemm<0><<<100, 256, GEMM_SMEM>>>(T1, nullptr, W_at2, nullptr, b_at2, nullptr,
                                      emat, nullptr, LBERT, LBERT);
    // e = sigmoid(v@W_e^T+b_e) | a = tanh(v@W_a^T+b_a) : dual launch, K=200
    tgemm<5><<<200, 256, GEMM_SMEM>>>(vb, nullptr, W_e, W_a, b_e, b_a,
                                      eb, ab, DIMS, DIMS);

    scan_kernel<<<dim3(8, BATCH), 256>>>(w_out, eb, ab, Mv0, mv_out, rb);

    // f = tanh(concat(read,k) @ W_f^T + b_f) : K=400 split at 200
    tgemm<2><<<100, 256, GEMM_SMEM>>>(rb, kb, W_f, nullptr, b_f, nullptr,
                                      fb, nullptr, 2 * DIMS, DIMS);
    // f_l = relu(concat(v, em_at) @ W_fus^T + b_fus) : K=400 split at 200
    tgemm<3><<<100, 256, GEMM_SMEM>>>(vb, emat, W_fus, nullptr, b_fus, nullptr,
                                      flb, nullptr, 2 * DIMS, DIMS);

    p_kernel<<<MR, 128>>>(fb, flb, W_p, b_p, p_out);
}

// round 5
// speedup vs baseline: 2.3309x; 1.1550x over previous
#include <cuda_runtime.h>
#include <cuda_bf16.h>
#include <cstdint>
#include <cstdio>

// ---------------- problem constants ----------------
#define BATCH   64
#define DIMS    200
#define SIZEM   50
#define NUMQ    10000
#define LBERT   512
#define HBERT   768

#define OFF_P   0
#define OFF_MV  (BATCH*DIMS)
#define OFF_W   (OFF_MV + BATCH*(DIMS+1)*SIZEM*DIMS)

// ---------------- scratch ----------------
__device__ float g_T1  [BATCH*DIMS*LBERT];   // T1 transposed: [B,200,512]
__device__ float g_emat[BATCH*DIMS*DIMS];
__device__ float g_k   [BATCH*DIMS*DIMS];
__device__ float g_v   [BATCH*DIMS*DIMS];
__device__ float g_e   [BATCH*DIMS*DIMS];
__device__ float g_a   [BATCH*DIMS*DIMS];
__device__ float g_read[BATCH*DIMS*DIMS];
__device__ float g_f   [BATCH*DIMS*DIMS];
__device__ float g_fl  [BATCH*DIMS*DIMS];

// precomputed bf16 hi/lo weights, layout [ch][n(200)][8]{bh0,bh1,bl0,bl1}
__device__ uint4 g_pw_at [24*200*8];
__device__ uint4 g_pw_at2[16*200*8];
__device__ uint4 g_pw_e  [ 7*200*8];
__device__ uint4 g_pw_a  [ 7*200*8];
__device__ uint4 g_pw_f  [13*200*8];
__device__ uint4 g_pw_fus[13*200*8];

// ================= low-level helpers =================
__device__ __forceinline__ void cp16(uint32_t saddr, const void* g) {
    asm volatile("cp.async.cg.shared.global [%0], [%1], 16;" :: "r"(saddr), "l"(g));
}
#define CP_COMMIT asm volatile("cp.async.commit_group;" ::: "memory")
#define CP_WAIT0  asm volatile("cp.async.wait_group 0;" ::: "memory")

__device__ __forceinline__ void mma16816(float* c, const uint32_t* a, uint32_t b0, uint32_t b1) {
    asm volatile("mma.sync.aligned.m16n8k16.row.col.f32.bf16.bf16.f32 "
        "{%0,%1,%2,%3}, {%4,%5,%6,%7}, {%8,%9}, {%0,%1,%2,%3};"
        : "+f"(c[0]), "+f"(c[1]), "+f"(c[2]), "+f"(c[3])
        : "r"(a[0]), "r"(a[1]), "r"(a[2]), "r"(a[3]), "r"(b0), "r"(b1));
}

__device__ __forceinline__ void split2(float x, float y, uint32_t& hi, uint32_t& lo) {
    __nv_bfloat16 hx = __float2bfloat16(x), hy = __float2bfloat16(y);
    float rx = x - __bfloat162float(hx), ry = y - __bfloat162float(hy);
    __nv_bfloat16 lx = __float2bfloat16(rx), ly = __float2bfloat16(ry);
    hi = (uint32_t)__bfloat16_as_ushort(hx) | ((uint32_t)__bfloat16_as_ushort(hy) << 16);
    lo = (uint32_t)__bfloat16_as_ushort(lx) | ((uint32_t)__bfloat16_as_ushort(ly) << 16);
}

// ---------------- weight precompute: fp32 [200,K] -> per-chunk bf16 hi/lo quads ----------------
__global__ void prep_w(const float* __restrict__ W, int K, int NC, uint4* __restrict__ out)
{
    int idx = blockIdx.x * 256 + threadIdx.x;
    int total = NC * 200 * 8;
    if (idx >= total) return;
    int sub = idx & 7;
    int n   = (idx >> 3) % 200;
    int ch  = idx / (200 * 8);
    int w0  = (sub >> 2) * 8 + (sub & 3);       // st*8 + tig
    int k   = ch * 32 + 2 * w0;
    const float* Wr = W + (size_t)n * K;
    float x0 = (k     < K) ? Wr[k]     : 0.f;
    float x1 = (k + 1 < K) ? Wr[k + 1] : 0.f;
    float x2 = (k + 8 < K) ? Wr[k + 8] : 0.f;
    float x3 = (k + 9 < K) ? Wr[k + 9] : 0.f;
    uint32_t h0, l0, h1, l1;
    split2(x0, x1, h0, l0);
    split2(x2, x3, h1, l1);
    uint4 v; v.x = h0; v.y = h1; v.z = l0; v.w = l1;
    out[idx] = v;
}

// ================= mma.sync bf16-split SGEMM =================
// Block 256 thr (8 warps), tile M=128 x N=(104|96), K-chunk 32, n-split via blockIdx.y.
#define SA_STRIDE 40                                  // fp32 per A row (32 used)
#define SBROW     48                                  // u32 per B n-row (32 used, pad->192B)
#define SM_BIAS   0
#define SM_A      1024                                // 2 * 128*40*4 = 40960
#define SM_B      (SM_A + 2*128*SA_STRIDE*4)          // 2 * 104*48*4 = 39936
#define GEMM_SMEM (SM_B + 2*104*SBROW*4)              // 81920

__device__ __forceinline__ void load_tileA(const float* __restrict__ A,
                                           const float* __restrict__ A2,
                                           int K, int Ksplit, int bm, int kstart,
                                           float* Afp, int tid)
{
    int kend = kstart + 32;
    bool s1 = (kend <= Ksplit);
    bool s2 = (kstart >= Ksplit) && (kend <= K);
    if (s1 || s2) {
        const float* base = s1 ? (A + (size_t)bm * Ksplit + kstart)
                               : (A2 + (size_t)bm * (K - Ksplit) + (kstart - Ksplit));
        size_t rs = s1 ? (size_t)Ksplit : (size_t)(K - Ksplit);
        uint32_t sb = (uint32_t)__cvta_generic_to_shared(Afp);
        #pragma unroll
        for (int pass = 0; pass < 4; ++pass) {
            int idx = tid + pass * 256;
            int row = idx >> 3, c4 = idx & 7;
            cp16(sb + (uint32_t)(row * SA_STRIDE + c4 * 4) * 4, base + (size_t)row * rs + c4 * 4);
        }
    } else {
        int K2 = K - Ksplit;
        for (int idx = tid; idx < 4096; idx += 256) {
            int row = idx >> 5, kk = idx & 31;
            int k = kstart + kk;
            float v = 0.f;
            if (k < K) v = (k < Ksplit) ? A[(size_t)(bm + row) * Ksplit + k]
                                        : A2[(size_t)(bm + row) * K2 + (k - Ksplit)];
            Afp[row * SA_STRIDE + kk] = v;
        }
    }
}

__device__ __forceinline__ void load_tileB(const uint4* __restrict__ pw, int ch, int n0,
                                           int nrows, uint32_t* Bsm, int tid)
{
    uint32_t sb = (uint32_t)__cvta_generic_to_shared(Bsm);
    const uint4* src = pw + ((size_t)ch * 200 + n0) * 8;
    int total = nrows * 8;
    for (int idx = tid; idx < total; idx += 256) {
        int n = idx >> 3, sub = idx & 7;
        cp16(sb + (uint32_t)(n * SBROW + sub * 4) * 4, src + (size_t)n * 8 + sub);
    }
}

// MODE: 0 none, 1 sigmoid, 2 tanh, 3 relu, 4 transposed-T1 store, 5 dual (z0 sig, z1 tanh)
template<int MODE>
__global__ void __launch_bounds__(256, 2)
tgemm(const float* __restrict__ A, const float* __restrict__ A2,
      const uint4* __restrict__ pwa, const uint4* __restrict__ pwb,
      const float* __restrict__ biasa, const float* __restrict__ biasb,
      float* __restrict__ Ca, float* __restrict__ Cb,
      int K, int Ksplit, int NC)
{
    extern __shared__ char smem[];
    float*    biasS = (float*)(smem + SM_BIAS);
    float*    Afp[2] = { (float*)(smem + SM_A), (float*)(smem + SM_A) + 128 * SA_STRIDE };
    uint32_t* Bsm[2] = { (uint32_t*)(smem + SM_B), (uint32_t*)(smem + SM_B) + 104 * SBROW };

    const int tid  = threadIdx.x;
    const int wid  = tid >> 5;
    const int lane = tid & 31;
    const int gid  = lane >> 2;
    const int tig  = lane & 3;
    const int warpM = wid * 16;

    const int n0  = blockIdx.y * 104;
    const int NFr = (blockIdx.y == 0) ? 13 : 12;
    const int bm  = blockIdx.x * 128;

    const uint4* pw = pwa;
    const float* bs = biasa;
    float* C = Ca;
    bool second = false;
    if (MODE == 5 && blockIdx.z == 1) { pw = pwb; bs = biasb; C = Cb; second = true; }

    for (int i = tid; i < 200; i += 256) biasS[i] = bs[i];

    // chunk 0
    load_tileA(A, A2, K, Ksplit, bm, 0, Afp[0], tid);
    load_tileB(pw, 0, n0, NFr * 8, Bsm[0], tid);
    CP_COMMIT;
    CP_WAIT0;
    __syncthreads();

    float c[13][4];
    #pragma unroll
    for (int i = 0; i < 13; ++i) { c[i][0] = 0.f; c[i][1] = 0.f; c[i][2] = 0.f; c[i][3] = 0.f; }

    for (int ch = 0; ch < NC; ++ch) {
        const float*    Acur = Afp[ch & 1];
        const uint32_t* Bcur = Bsm[ch & 1];
        if (ch + 1 < NC) {
            load_tileA(A, A2, K, Ksplit, bm, (ch + 1) * 32, Afp[(ch + 1) & 1], tid);
            load_tileB(pw, ch + 1, n0, NFr * 8, Bsm[(ch + 1) & 1], tid);
            CP_COMMIT;
        }
        #pragma unroll
        for (int st = 0; st < 2; ++st) {
            const int koff = st * 16;
            uint32_t ah[4], al[4];
            #pragma unroll
            for (int i = 0; i < 4; ++i) {
                int rr = warpM + gid + (i & 1) * 8;
                int kk = koff + 2 * tig + ((i >> 1) * 8);
                float2 v = *(const float2*)&Acur[rr * SA_STRIDE + kk];
                split2(v.x, v.y, ah[i], al[i]);
            }
            #pragma unroll
            for (int nf = 0; nf < 13; ++nf) {
                if (nf < NFr) {
                    const uint4 bv = *(const uint4*)&Bcur[(nf * 8 + gid) * SBROW + st * 16 + tig * 4];
                    mma16816(c[nf], ah, bv.x, bv.y);
                    mma16816(c[nf], ah, bv.z, bv.w);
                    mma16816(c[nf], al, bv.x, bv.y);
                }
            }
        }
        if (ch + 1 < NC) {
            CP_WAIT0;
            __syncthreads();
        }
    }

    // ---------------- epilogue ----------------
    const int m0 = bm + warpM + gid;
    #pragma unroll
    for (int nf = 0; nf < 13; ++nf) {
        if (nf >= NFr) break;
        int n = n0 + nf * 8 + 2 * tig;
        float b0v = biasS[n], b1v = biasS[n + 1];
        float v00 = c[nf][0] + b0v, v01 = c[nf][1] + b1v;
        float v10 = c[nf][2] + b0v, v11 = c[nf][3] + b1v;
        if (MODE == 1) {
            v00 = 1.f / (1.f + expf(-v00)); v01 = 1.f / (1.f + expf(-v01));
            v10 = 1.f / (1.f + expf(-v10)); v11 = 1.f / (1.f + expf(-v11));
        } else if (MODE == 2) {
            v00 = tanhf(v00); v01 = tanhf(v01); v10 = tanhf(v10); v11 = tanhf(v11);
        } else if (MODE == 3) {
            v00 = fmaxf(v00, 0.f); v01 = fmaxf(v01, 0.f);
            v10 = fmaxf(v10, 0.f); v11 = fmaxf(v11, 0.f);
        } else if (MODE == 5) {
            if (second) { v00 = tanhf(v00); v01 = tanhf(v01); v10 = tanhf(v10); v11 = tanhf(v11); }
            else {
                v00 = 1.f / (1.f + expf(-v00)); v01 = 1.f / (1.f + expf(-v01));
                v10 = 1.f / (1.f + expf(-v10)); v11 = 1.f / (1.f + expf(-v11));
            }
        }
        if (MODE == 4) {
            int b = bm >> 9;
            int l = (bm & 511) + warpM + gid;
            float* base = C + ((size_t)b * 200 + n) * 512;
            base[l] = v00;
            base[512 + l] = v01;
            base[l + 8] = v10;
            base[512 + l + 8] = v11;
        } else {
            float2 lo2 = {v00, v01}, hi2 = {v10, v11};
            *(float2*)&C[(size_t)m0 * 200 + n] = lo2;
            *(float2*)&C[(size_t)(m0 + 8) * 200 + n] = hi2;
        }
    }
}

// ---------------- gather v rows ----------------
__global__ void gather_v_kernel(const int* __restrict__ q, const int* __restrict__ r,
                                const float* __restrict__ v_emb, float* __restrict__ vbuf)
{
    int m   = blockIdx.x;
    int tid = threadIdx.x;
    int x   = q[m] + NUMQ * r[m];
    const float4* src = (const float4*)(v_emb + (size_t)x * DIMS);
    float4*       dst = (float4*)(vbuf + (size_t)m * DIMS);
    for (int i = tid; i < DIMS / 4; i += 64) dst[i] = src[i];
}

// ---------------- w = softmax(k @ Mk^T), fused k gather ----------------
__global__ void wk_kernel(const int* __restrict__ q, const float* __restrict__ k_emb,
                          const float* __restrict__ Mk,
                          float* __restrict__ wOut, float* __restrict__ kbuf)
{
    int m   = blockIdx.x;
    int tid = threadIdx.x;                 // 256
    __shared__ float krow[DIMS];
    __shared__ float part4[200];
    __shared__ float logits[SIZEM];
    __shared__ float sm_max, sm_sum;

    int qi = q[m];
    if (tid < DIMS) {
        float val = k_emb[(size_t)qi * DIMS + tid];
        krow[tid] = val;
        kbuf[(size_t)m * DIMS + tid] = val;
    }
    __syncthreads();

    if (tid < 200) {
        int s = tid >> 2, g = tid & 3;
        const float* mk = Mk + s * DIMS + g * 50;
        const float* kr = krow + g * 50;
        float acc = 0.f;
        #pragma unroll 10
        for (int kk = 0; kk < 50; ++kk) acc = fmaf(kr[kk], __ldg(&mk[kk]), acc);
        part4[tid] = acc;
    }
    __syncthreads();
    if (tid < SIZEM)
        logits[tid] = part4[4 * tid] + part4[4 * tid + 1] + part4[4 * tid + 2] + part4[4 * tid + 3];
    __syncthreads();
    if (tid < 32) {
        float v = logits[tid];
        if (tid + 32 < SIZEM) v = fmaxf(v, logits[tid + 32]);
        #pragma unroll
        for (int o = 16; o > 0; o >>= 1) v = fmaxf(v, __shfl_xor_sync(0xffffffff, v, o));
        if (tid == 0) sm_max = v;
    }
    __syncthreads();
    if (tid < SIZEM) logits[tid] = expf(logits[tid] - sm_max);
    __syncthreads();
    if (tid < 32) {
        float v = (tid < SIZEM) ? logits[tid] : 0.f;
        if (tid + 32 < SIZEM) v += logits[tid + 32];
        #pragma unroll
        for (int o = 16; o > 0; o >>= 1) v += __shfl_xor_sync(0xffffffff, v, o);
        if (tid == 0) sm_sum = v;
    }
    __syncthreads();
    if (tid < SIZEM) wOut[(size_t)m * SIZEM + tid] = logits[tid] / sm_sum;
}

// ---------------- memory scan ----------------
__global__ void scan_kernel(const float* __restrict__ w,
                            const float* __restrict__ e,
                            const float* __restrict__ a,
                            const float* __restrict__ Mv0,
                            float* __restrict__ MvOut,
                            float* __restrict__ readOut)
{
    const int cs = blockIdx.x;            // 0..7
    const int b  = blockIdx.y;
    const int j0 = cs * 25;
    __shared__ float Mv_s[SIZEM * 25];
    __shared__ float w_s[SIZEM], e_s[25], a_s[25];
    __shared__ float part[8 * 25];
    const int tid = threadIdx.x;

    for (int idx = tid; idx < SIZEM * 25; idx += 256) {
        int s = idx / 25, j = idx % 25;
        Mv_s[idx] = Mv0[s * DIMS + j0 + j];
    }

    const int sg = tid / 25;
    const int j  = tid % 25;
    const int cnt = 6 + (sg < 2 ? 1 : 0);
    const int sst = sg * 6 + min(sg, 2);

    float r_w = 0.f, r_e = 0.f, r_a = 0.f;
    if (tid < SIZEM) r_w = w[(size_t)b * DIMS * SIZEM + tid];
    if (tid < 25) {
        r_e = e[(size_t)b * DIMS * DIMS + j0 + tid];
        r_a = a[(size_t)b * DIMS * DIMS + j0 + tid];
    }
    __syncthreads();

    for (int t = 0; t < DIMS; ++t) {
        if (tid < SIZEM) w_s[tid] = r_w;
        if (tid < 25) { e_s[tid] = r_e; a_s[tid] = r_a; }
        if (t > 0 && tid >= 200 && tid < 225) {
            int j2 = tid - 200;
            float s0 = part[j2] + part[25 + j2] + part[50 + j2] + part[75 + j2]
                     + part[100 + j2] + part[125 + j2] + part[150 + j2] + part[175 + j2];
            readOut[((size_t)b * DIMS + (t - 1)) * DIMS + j0 + j2] = s0;
        }
        __syncthreads();

        if (t + 1 < DIMS) {
            if (tid < SIZEM) r_w = w[((size_t)b * DIMS + t + 1) * SIZEM + tid];
            if (tid < 25) {
                r_e = e[((size_t)b * DIMS + t + 1) * DIMS + j0 + tid];
                r_a = a[((size_t)b * DIMS + t + 1) * DIMS + j0 + tid];
            }
        }

        if (tid < 200) {
            float accum = 0.f;
            float ej = e_s[j], aj = a_s[j];
            float* outb = MvOut + ((size_t)(b * (DIMS + 1) + t) * SIZEM) * DIMS + j0 + j;
            #pragma unroll 7
            for (int s = sst; s < sst + cnt; ++s) {
                float m  = Mv_s[s * 25 + j];
                float wv = w_s[s];
                outb[(size_t)s * DIMS] = m;
                accum = fmaf(wv, m, accum);
                Mv_s[s * 25 + j] = fmaf(wv, fmaf(-ej, m, aj), m);
            }
            part[sg * 25 + j] = accum;
        }
        __syncthreads();
    }

    if (tid >= 200 && tid < 225) {
        int j2 = tid - 200;
        float s0 = part[j2] + part[25 + j2] + part[50 + j2] + part[75 + j2]
                 + part[100 + j2] + part[125 + j2] + part[150 + j2] + part[175 + j2];
        readOut[((size_t)b * DIMS + 199) * DIMS + j0 + j2] = s0;
    }
    for (int idx = tid; idx < SIZEM * 25; idx += 256) {
        int s = idx / 25, jj = idx % 25;
        MvOut[((size_t)(b * (DIMS + 1) + DIMS) * SIZEM + s) * DIMS + j0 + jj] = Mv_s[idx];
    }
}

// ---------------- final p ----------------
__global__ void p_kernel(const float* __restrict__ f, const float* __restrict__ fl,
                         const float* __restrict__ Wp, const float* __restrict__ bp,
                         float* __restrict__ pOut)
{
    int bt = blockIdx.x;
    int b  = bt / DIMS, t = bt % DIMS;
    int tid = threadIdx.x;                // 128
    float acc = 0.f;
    for (int c = tid; c < 2 * DIMS; c += 128) {
        float xv = (c < DIMS) ? f[(size_t)bt * DIMS + c]
                              : fl[((size_t)b * DIMS + (c - DIMS)) * DIMS + t];
        acc = fmaf(Wp[c], xv, acc);
    }
    __shared__ float red[128];
    red[tid] = acc;
    __syncthreads();
    #pragma unroll
    for (int s = 64; s > 0; s >>= 1) {
        if (tid < s) red[tid] += red[tid + s];
        __syncthreads();
    }
    if (tid == 0) pOut[bt] = 1.f / (1.f + expf(-(red[0] + bp[0])));
}

// ---------------- launcher ----------------
extern "C" void kernel_launch(void* const* d_in, const int* in_sizes, int n_in,
                              void* d_out, int out_size)
{
    const int*   q     = (const int*)d_in[0];
    const int*   r     = (const int*)d_in[1];
    const float* bert  = (const float*)d_in[2];
    const float* k_emb = (const float*)d_in[3];
    const float* v_emb = (const float*)d_in[4];
    const float* Mk    = (const float*)d_in[5];
    const float* Mv0   = (const float*)d_in[6];
    const float* W_at  = (const float*)d_in[7];
    const float* b_at  = (const float*)d_in[8];
    const float* W_at2 = (const float*)d_in[9];
    const float* b_at2 = (const float*)d_in[10];
    const float* W_fus = (const float*)d_in[11];
    const float* b_fus = (const float*)d_in[12];
    const float* W_e   = (const float*)d_in[13];
    const float* b_e   = (const float*)d_in[14];
    const float* W_a   = (const float*)d_in[15];
    const float* b_a   = (const float*)d_in[16];
    const float* W_f   = (const float*)d_in[17];
    const float* b_f   = (const float*)d_in[18];
    const float* W_p   = (const float*)d_in[19];
    const float* b_p   = (const float*)d_in[20];

    float* out    = (float*)d_out;
    float* p_out  = out + OFF_P;
    float* mv_out = out + OFF_MV;
    float* w_out  = out + OFF_W;

    float *T1, *emat, *kb, *vb, *eb, *ab, *rb, *fb, *flb;
    cudaGetSymbolAddress((void**)&T1,   g_T1);
    cudaGetSymbolAddress((void**)&emat, g_emat);
    cudaGetSymbolAddress((void**)&kb,   g_k);
    cudaGetSymbolAddress((void**)&vb,   g_v);
    cudaGetSymbolAddress((void**)&eb,   g_e);
    cudaGetSymbolAddress((void**)&ab,   g_a);
    cudaGetSymbolAddress((void**)&rb,   g_read);
    cudaGetSymbolAddress((void**)&fb,   g_f);
    cudaGetSymbolAddress((void**)&flb,  g_fl);

    uint4 *pw_at, *pw_at2, *pw_e, *pw_a, *pw_f, *pw_fus;
    cudaGetSymbolAddress((void**)&pw_at,  g_pw_at);
    cudaGetSymbolAddress((void**)&pw_at2, g_pw_at2);
    cudaGetSymbolAddress((void**)&pw_e,   g_pw_e);
    cudaGetSymbolAddress((void**)&pw_a,   g_pw_a);
    cudaGetSymbolAddress((void**)&pw_f,   g_pw_f);
    cudaGetSymbolAddress((void**)&pw_fus, g_pw_fus);

    cudaFuncSetAttribute(tgemm<0>, cudaFuncAttributeMaxDynamicSharedMemorySize, GEMM_SMEM);
    cudaFuncSetAttribute(tgemm<2>, cudaFuncAttributeMaxDynamicSharedMemorySize, GEMM_SMEM);
    cudaFuncSetAttribute(tgemm<3>, cudaFuncAttributeMaxDynamicSharedMemorySize, GEMM_SMEM);
    cudaFuncSetAttribute(tgemm<4>, cudaFuncAttributeMaxDynamicSharedMemorySize, GEMM_SMEM);
    cudaFuncSetAttribute(tgemm<5>, cudaFuncAttributeMaxDynamicSharedMemorySize, GEMM_SMEM);

    const int MR = BATCH * DIMS;          // 12800

    // weight precompute (bf16 hi/lo quads)
    prep_w<<<(24*200*8 + 255)/256, 256>>>(W_at,  HBERT,    24, pw_at);
    prep_w<<<(16*200*8 + 255)/256, 256>>>(W_at2, LBERT,    16, pw_at2);
    prep_w<<<( 7*200*8 + 255)/256, 256>>>(W_e,   DIMS,      7, pw_e);
    prep_w<<<( 7*200*8 + 255)/256, 256>>>(W_a,   DIMS,      7, pw_a);
    prep_w<<<(13*200*8 + 255)/256, 256>>>(W_f,   2*DIMS,   13, pw_f);
    prep_w<<<(13*200*8 + 255)/256, 256>>>(W_fus, 2*DIMS,   13, pw_fus);

    gather_v_kernel<<<MR, 64>>>(q, r, v_emb, vb);
    wk_kernel<<<MR, 256>>>(q, k_emb, Mk, w_out, kb);

    // T1t[b,i,l] = (bert @ W_at^T + b_at)^T : M=32768, K=768, NC=24
    tgemm<4><<<dim3(256, 2), 256, GEMM_SMEM>>>(bert, nullptr, pw_at, nullptr, b_at, nullptr,
                                               T1, nullptr, HBERT, HBERT, 24);
    // em_at = T1t @ W_at2^T + b_at2 : M=12800, K=512, NC=16
    tgemm<0><<<dim3(100, 2), 256, GEMM_SMEM>>>(T1, nullptr, pw_at2, nullptr, b_at2, nullptr,
                                               emat, nullptr, LBERT, LBERT, 16);
    // e = sigmoid(v@W_e^T+b_e) | a = tanh(v@W_a^T+b_a) : dual via z, K=200, NC=7
    tgemm<5><<<dim3(100, 2, 2), 256, GEMM_SMEM>>>(vb, nullptr, pw_e, pw_a, b_e, b_a,
                                                  eb, ab, DIMS, DIMS, 7);

    scan_kernel<<<dim3(8, BATCH), 256>>>(w_out, eb, ab, Mv0, mv_out, rb);

    // f = tanh(concat(read,k) @ W_f^T + b_f) : K=400 split 200, NC=13
    tgemm<2><<<dim3(100, 2), 256, GEMM_SMEM>>>(rb, kb, pw_f, nullptr, b_f, nullptr,
                                               fb, nullptr, 2 * DIMS, DIMS, 13);
    // f_l = relu(concat(v, em_at) @ W_fus^T + b_fus) : K=400 split 200, NC=13
    tgemm<3><<<dim3(100, 2), 256, GEMM_SMEM>>>(vb, emat, pw_fus, nullptr, b_fus, nullptr,
                                               flb, nullptr, 2 * DIMS, DIMS, 13);

    p_kernel<<<MR, 128>>>(fb, flb, W_p, b_p, p_out);
}